// round 1
// baseline (speedup 1.0000x reference)
#include <cuda_runtime.h>

#define NN 4096
#define DD 128
#define TS 128          // output tile (TS x TS) per CTA
#define KC 32           // k-chunk staged through shared
#define SPITCH 132      // padded shared pitch (floats) to dodge STS bank conflicts

// 64MB scratch for the sim matrix + per-row losses (device globals: allowed scratch)
__device__ float g_sim[(size_t)NN * NN];
__device__ float g_rowloss[NN];

// ---------------------------------------------------------------------------
// packed f32x2 helpers (sm_103a: FFMA2 only reachable via PTX fma.rn.f32x2)
// ---------------------------------------------------------------------------
__device__ __forceinline__ unsigned long long fma2(unsigned long long a,
                                                   unsigned long long b,
                                                   unsigned long long c) {
    unsigned long long d;
    asm("fma.rn.f32x2 %0, %1, %2, %3;" : "=l"(d) : "l"(a), "l"(b), "l"(c));
    return d;
}
__device__ __forceinline__ unsigned long long pack2(float x) {
    unsigned long long r;
    asm("mov.b64 %0, {%1, %1};" : "=l"(r) : "f"(x));
    return r;
}

// ---------------------------------------------------------------------------
// Kernel 1: sim = X @ X^T   (fp32, f32x2 packed FFMA)
// 128x128 tile / CTA, 256 threads, 8x8 micro-tile per thread (as 8x4 f32x2).
// ---------------------------------------------------------------------------
__global__ __launch_bounds__(256) void gemm_xxt(const float* __restrict__ X) {
    __shared__ float As[KC * SPITCH];   // k-major: As[k][m]
    __shared__ float Bs[KC * SPITCH];

    const int tid = threadIdx.x;
    const int tx = tid & 15;       // 0..15  -> 8 output cols each
    const int ty = tid >> 4;       // 0..15  -> 8 output rows each
    const int br = blockIdx.y * TS;
    const int bc = blockIdx.x * TS;

    unsigned long long acc[8][4];
    #pragma unroll
    for (int m = 0; m < 8; m++)
        #pragma unroll
        for (int q = 0; q < 4; q++) acc[m][q] = 0ull;

    #pragma unroll 1
    for (int kc = 0; kc < DD; kc += KC) {
        // cooperative load, transposed into k-major shared
        #pragma unroll
        for (int it = 0; it < 4; it++) {
            int idx = tid + it * 256;          // 0..1023
            int m   = idx >> 3;                // 0..127 tile row
            int k4  = (idx & 7) << 2;          // 0,4,...,28
            float4 a = *(const float4*)(X + (size_t)(br + m) * DD + kc + k4);
            float4 b = *(const float4*)(X + (size_t)(bc + m) * DD + kc + k4);
            As[(k4 + 0) * SPITCH + m] = a.x;
            As[(k4 + 1) * SPITCH + m] = a.y;
            As[(k4 + 2) * SPITCH + m] = a.z;
            As[(k4 + 3) * SPITCH + m] = a.w;
            Bs[(k4 + 0) * SPITCH + m] = b.x;
            Bs[(k4 + 1) * SPITCH + m] = b.y;
            Bs[(k4 + 2) * SPITCH + m] = b.z;
            Bs[(k4 + 3) * SPITCH + m] = b.w;
        }
        __syncthreads();

        #pragma unroll
        for (int k = 0; k < KC; k++) {
            const float4* Ap = (const float4*)(As + k * SPITCH + ty * 8);
            float4 a0 = Ap[0], a1 = Ap[1];
            const ulonglong2* Bp = (const ulonglong2*)(Bs + k * SPITCH + tx * 8);
            ulonglong2 bb0 = Bp[0], bb1 = Bp[1];
            unsigned long long b0 = bb0.x, b1 = bb0.y, b2 = bb1.x, b3 = bb1.y;
            float av[8] = {a0.x, a0.y, a0.z, a0.w, a1.x, a1.y, a1.z, a1.w};
            #pragma unroll
            for (int m = 0; m < 8; m++) {
                unsigned long long am = pack2(av[m]);
                acc[m][0] = fma2(am, b0, acc[m][0]);
                acc[m][1] = fma2(am, b1, acc[m][1]);
                acc[m][2] = fma2(am, b2, acc[m][2]);
                acc[m][3] = fma2(am, b3, acc[m][3]);
            }
        }
        __syncthreads();
    }

    #pragma unroll
    for (int m = 0; m < 8; m++) {
        float* dst = g_sim + (size_t)(br + ty * 8 + m) * NN + bc + tx * 8;
        ulonglong2 v0; v0.x = acc[m][0]; v0.y = acc[m][1];
        ulonglong2 v1; v1.x = acc[m][2]; v1.y = acc[m][3];
        *(ulonglong2*)(dst)     = v0;
        *(ulonglong2*)(dst + 4) = v1;
    }
}

// ---------------------------------------------------------------------------
// Kernel 2: per-row stats + loss. One CTA (256 threads) per row.
// ---------------------------------------------------------------------------
__device__ __forceinline__ float warpSum(float v) {
    #pragma unroll
    for (int o = 16; o > 0; o >>= 1) v += __shfl_down_sync(0xffffffffu, v, o);
    return v;
}
__device__ __forceinline__ float warpMin(float v) {
    #pragma unroll
    for (int o = 16; o > 0; o >>= 1) v = fminf(v, __shfl_down_sync(0xffffffffu, v, o));
    return v;
}
// numerically stable softplus; matches fp32 log1p(exp(x)) to ~1e-6 rel on sums
__device__ __forceinline__ float sp_f(float x) {
    float e = __expf(-fabsf(x));
    return fmaxf(x, 0.0f) + __logf(1.0f + e);
}

__global__ __launch_bounds__(256) void row_loss(const int* __restrict__ ni_ptr) {
    __shared__ float srow[NN];        // 16KB: cached sim row
    __shared__ float red[6][8];
    __shared__ float params[3];

    const int i   = blockIdx.x;
    const int tid = threadIdx.x;
    const int ni  = ni_ptr ? *ni_ptr : 8;   // low word valid for int32 or int64 (LE)
    const int lo  = (i / ni) * ni;
    const int hi  = lo + ni;
    const float* row = g_sim + (size_t)i * NN;

    // pass 1: stats
    float pos_sum = 0.f, pos_sq = 0.f, pos_min = 1e30f, pos_cnt = 0.f;
    float neg_sum = 0.f, neg_sq = 0.f;
    for (int j = tid; j < NN; j += 256) {
        float s = row[j];
        srow[j] = s;
        if (j == i) continue;
        if (j >= lo && j < hi) {
            pos_sum += s; pos_sq += s * s;
            pos_min = fminf(pos_min, s); pos_cnt += 1.f;
        } else {
            neg_sum += s; neg_sq += s * s;
        }
    }
    pos_sum = warpSum(pos_sum); pos_sq = warpSum(pos_sq); pos_min = warpMin(pos_min);
    pos_cnt = warpSum(pos_cnt); neg_sum = warpSum(neg_sum); neg_sq = warpSum(neg_sq);
    const int lane = tid & 31, w = tid >> 5;
    if (lane == 0) {
        red[0][w] = pos_sum; red[1][w] = pos_sq; red[2][w] = pos_min;
        red[3][w] = pos_cnt; red[4][w] = neg_sum; red[5][w] = neg_sq;
    }
    __syncthreads();
    if (tid == 0) {
        float ps = 0.f, pq = 0.f, pm = 1e30f, pc = 0.f, ns = 0.f, nq = 0.f;
        #pragma unroll
        for (int q = 0; q < 8; q++) {
            ps += red[0][q]; pq += red[1][q]; pm = fminf(pm, red[2][q]);
            pc += red[3][q]; ns += red[4][q]; nq += red[5][q];
        }
        float kf  = pc;
        float ncf = (float)(NN - 1) - pc;
        float pmean = ps / kf;
        float pstd  = sqrtf(fmaxf(pq / kf - pmean * pmean, 0.f));
        float nmean = ns / ncf;
        float nstd  = sqrtf(fmaxf(nq / ncf - nmean * nmean, 0.f));
        float inter = (nstd * pmean + pstd * nmean) / (pstd + nstd);
        inter = 0.8f * inter + 0.1f;
        params[0] = inter;
        params[1] = pm - 0.05f;   // keep threshold
        params[2] = kf;
    }
    __syncthreads();
    const float inter = params[0], thr = params[1], kf = params[2];

    // pass 2: losses (from shared)
    float pl = 0.f, nl = 0.f, cnt = 0.f;
    for (int j = tid; j < NN; j += 256) {
        if (j == i) continue;
        float s = srow[j];
        if (j >= lo && j < hi) {
            pl += sp_f(10.f * (inter - s));            // log1p(exp(-10*(pos-inter)))
        } else if (s > thr) {
            nl += sp_f(40.f * (s - inter));
            cnt += 1.f;
        }
    }
    pl = warpSum(pl); nl = warpSum(nl); cnt = warpSum(cnt);
    if (lane == 0) { red[0][w] = pl; red[1][w] = nl; red[2][w] = cnt; }
    __syncthreads();
    if (tid == 0) {
        float a = 0.f, b = 0.f, c = 0.f;
        #pragma unroll
        for (int q = 0; q < 8; q++) { a += red[0][q]; b += red[1][q]; c += red[2][q]; }
        g_rowloss[i] = 0.2f * a / kf + 0.05f * b / fmaxf(c, 1.f);
    }
}

// ---------------------------------------------------------------------------
// Kernel 3: deterministic final reduction
// ---------------------------------------------------------------------------
__global__ __launch_bounds__(256) void final_reduce(float* __restrict__ out) {
    __shared__ float sh[256];
    const int tid = threadIdx.x;
    float v = 0.f;
    for (int j = tid; j < NN; j += 256) v += g_rowloss[j];
    sh[tid] = v;
    __syncthreads();
    #pragma unroll
    for (int s = 128; s > 0; s >>= 1) {
        if (tid < s) sh[tid] += sh[tid + s];
        __syncthreads();
    }
    if (tid == 0) out[0] = sh[0] * (1.0f / NN);
}

// ---------------------------------------------------------------------------
extern "C" void kernel_launch(void* const* d_in, const int* in_sizes, int n_in,
                              void* d_out, int out_size) {
    const float* X = (const float*)d_in[0];
    const int* ni_ptr = (n_in > 2) ? (const int*)d_in[2] : nullptr;

    dim3 grid(NN / TS, NN / TS);
    gemm_xxt<<<grid, 256>>>(X);
    row_loss<<<NN, 256>>>(ni_ptr);
    final_reduce<<<1, 256>>>((float*)d_out);
}

// round 2
// speedup vs baseline: 1.5210x; 1.5210x over previous
#include <cuda_runtime.h>

#define NN 4096
#define DD 128
#define TS 128          // output tile (TS x TS) per CTA
#define KC 32           // k-chunk staged through shared
#define SPITCH 132      // padded shared pitch (floats)
#define NTILE (NN / TS) // 32
#define NTRI  (NTILE * (NTILE + 1) / 2)  // 528 upper-tri tiles

__device__ float g_sim[(size_t)NN * NN];
__device__ float g_rowloss[NN];

// ---------------------------------------------------------------------------
// packed f32x2 helpers
// ---------------------------------------------------------------------------
__device__ __forceinline__ unsigned long long fma2(unsigned long long a,
                                                   unsigned long long b,
                                                   unsigned long long c) {
    unsigned long long d;
    asm("fma.rn.f32x2 %0, %1, %2, %3;" : "=l"(d) : "l"(a), "l"(b), "l"(c));
    return d;
}
__device__ __forceinline__ unsigned long long pack2(float x) {
    unsigned long long r;
    asm("mov.b64 %0, {%1, %1};" : "=l"(r) : "f"(x));
    return r;
}

// ---------------------------------------------------------------------------
// Kernel 1: sim = X @ X^T, upper-triangular tiles only (symmetric write-back)
// ---------------------------------------------------------------------------
__global__ __launch_bounds__(256) void gemm_xxt(const float* __restrict__ X) {
    __shared__ float As[KC * SPITCH];   // k-major: As[k][m]
    __shared__ float Bs[KC * SPITCH];

    // decode linear triangular index -> (by, bx) with bx >= by
    int rem = blockIdx.x;
    int by = 0;
    while (rem >= (NTILE - by)) { rem -= (NTILE - by); by++; }
    const int bx = by + rem;

    const int tid = threadIdx.x;
    const int tx = tid & 15;
    const int ty = tid >> 4;
    const int br = by * TS;
    const int bc = bx * TS;

    unsigned long long acc[8][4];
    #pragma unroll
    for (int m = 0; m < 8; m++)
        #pragma unroll
        for (int q = 0; q < 4; q++) acc[m][q] = 0ull;

    #pragma unroll 1
    for (int kc = 0; kc < DD; kc += KC) {
        #pragma unroll
        for (int it = 0; it < 4; it++) {
            int idx = tid + it * 256;
            int m   = idx >> 3;
            int k4  = (idx & 7) << 2;
            float4 a = *(const float4*)(X + (size_t)(br + m) * DD + kc + k4);
            float4 b = *(const float4*)(X + (size_t)(bc + m) * DD + kc + k4);
            As[(k4 + 0) * SPITCH + m] = a.x;
            As[(k4 + 1) * SPITCH + m] = a.y;
            As[(k4 + 2) * SPITCH + m] = a.z;
            As[(k4 + 3) * SPITCH + m] = a.w;
            Bs[(k4 + 0) * SPITCH + m] = b.x;
            Bs[(k4 + 1) * SPITCH + m] = b.y;
            Bs[(k4 + 2) * SPITCH + m] = b.z;
            Bs[(k4 + 3) * SPITCH + m] = b.w;
        }
        __syncthreads();

        #pragma unroll
        for (int k = 0; k < KC; k++) {
            const float4* Ap = (const float4*)(As + k * SPITCH + ty * 8);
            float4 a0 = Ap[0], a1 = Ap[1];
            const ulonglong2* Bp = (const ulonglong2*)(Bs + k * SPITCH + tx * 8);
            ulonglong2 bb0 = Bp[0], bb1 = Bp[1];
            unsigned long long b0 = bb0.x, b1 = bb0.y, b2 = bb1.x, b3 = bb1.y;
            float av[8] = {a0.x, a0.y, a0.z, a0.w, a1.x, a1.y, a1.z, a1.w};
            #pragma unroll
            for (int m = 0; m < 8; m++) {
                unsigned long long am = pack2(av[m]);
                acc[m][0] = fma2(am, b0, acc[m][0]);
                acc[m][1] = fma2(am, b1, acc[m][1]);
                acc[m][2] = fma2(am, b2, acc[m][2]);
                acc[m][3] = fma2(am, b3, acc[m][3]);
            }
        }
        __syncthreads();
    }

    // normal store: rows br+ty*8+m, cols bc+tx*8..+7
    #pragma unroll
    for (int m = 0; m < 8; m++) {
        float* dst = g_sim + (size_t)(br + ty * 8 + m) * NN + bc + tx * 8;
        ulonglong2 v0; v0.x = acc[m][0]; v0.y = acc[m][1];
        ulonglong2 v1; v1.x = acc[m][2]; v1.y = acc[m][3];
        *(ulonglong2*)(dst)     = v0;
        *(ulonglong2*)(dst + 4) = v1;
    }

    // transposed store for off-diagonal tiles: rows bc+tx*8+n, cols br+ty*8..+7
    if (bx != by) {
        float af[8][8];
        #pragma unroll
        for (int m = 0; m < 8; m++)
            #pragma unroll
            for (int q = 0; q < 4; q++) {
                float2 p = *(float2*)&acc[m][q];
                af[m][2 * q]     = p.x;
                af[m][2 * q + 1] = p.y;
            }
        #pragma unroll
        for (int n = 0; n < 8; n++) {
            float* dst = g_sim + (size_t)(bc + tx * 8 + n) * NN + br + ty * 8;
            float4 v0 = make_float4(af[0][n], af[1][n], af[2][n], af[3][n]);
            float4 v1 = make_float4(af[4][n], af[5][n], af[6][n], af[7][n]);
            ((float4*)dst)[0] = v0;
            ((float4*)dst)[1] = v1;
        }
    }
}

// ---------------------------------------------------------------------------
// Kernel 2: per-row stats + loss. One CTA (256 threads) per row.
// ---------------------------------------------------------------------------
__device__ __forceinline__ float warpSum(float v) {
    #pragma unroll
    for (int o = 16; o > 0; o >>= 1) v += __shfl_down_sync(0xffffffffu, v, o);
    return v;
}
__device__ __forceinline__ float sp_f(float x) {
    float e = __expf(-fabsf(x));
    return fmaxf(x, 0.0f) + __logf(1.0f + e);
}

__global__ __launch_bounds__(256) void row_loss(const int* __restrict__ ni_ptr) {
    __shared__ float srow[NN];
    __shared__ float red[2][8];
    __shared__ float params[3];

    const int i   = blockIdx.x;
    const int tid = threadIdx.x;
    const int ni  = ni_ptr ? *ni_ptr : 8;
    const int lo  = (i / ni) * ni;
    const int hi  = lo + ni;
    const float4* row4 = (const float4*)(g_sim + (size_t)i * NN);

    // pass 1: branch-free full-row sum / sumsq (includes self + positives)
    float sum = 0.f, sq = 0.f;
    for (int j4 = tid; j4 < NN / 4; j4 += 256) {
        float4 v = row4[j4];
        ((float4*)srow)[j4] = v;
        sum += (v.x + v.y) + (v.z + v.w);
        sq  += (v.x * v.x + v.y * v.y) + (v.z * v.z + v.w * v.w);
    }
    sum = warpSum(sum); sq = warpSum(sq);
    const int lane = tid & 31, w = tid >> 5;
    if (lane == 0) { red[0][w] = sum; red[1][w] = sq; }
    __syncthreads();
    if (tid == 0) {
        float S = 0.f, Q = 0.f;
        #pragma unroll
        for (int q = 0; q < 8; q++) { S += red[0][q]; Q += red[1][q]; }
        // class-block stats (positives are consecutive indices lo..hi-1)
        float ps = 0.f, pq = 0.f, pm = 1e30f;
        for (int j = lo; j < hi; j++) {
            if (j == i) continue;
            float s = srow[j];
            ps += s; pq += s * s; pm = fminf(pm, s);
        }
        float sii = srow[i];
        float kf  = (float)(ni - 1);
        float ncf = (float)(NN - ni);
        float ns = S - ps - sii;
        float nq = Q - pq - sii * sii;
        float pmean = ps / kf;
        float pstd  = sqrtf(fmaxf(pq / kf - pmean * pmean, 0.f));
        float nmean = ns / ncf;
        float nstd  = sqrtf(fmaxf(nq / ncf - nmean * nmean, 0.f));
        float inter = (nstd * pmean + pstd * nmean) / (pstd + nstd);
        inter = 0.8f * inter + 0.1f;
        params[0] = inter;
        params[1] = pm - 0.05f;
        params[2] = kf;
    }
    __syncthreads();
    const float inter = params[0], thr = params[1], kf = params[2];

    // pass 2: negatives from shared (vectorized, skip the class block per-lane)
    float nl = 0.f, cnt = 0.f;
    for (int j4 = tid; j4 < NN / 4; j4 += 256) {
        float4 v = ((const float4*)srow)[j4];
        int jb = j4 * 4;
        float vs[4] = {v.x, v.y, v.z, v.w};
        #pragma unroll
        for (int e = 0; e < 4; e++) {
            int j = jb + e;
            bool inblk = (j >= lo) & (j < hi);
            float s = vs[e];
            if (!inblk && s > thr) {
                nl += sp_f(40.f * (s - inter));
                cnt += 1.f;
            }
        }
    }
    nl = warpSum(nl); cnt = warpSum(cnt);
    if (lane == 0) { red[0][w] = nl; red[1][w] = cnt; }
    __syncthreads();
    if (tid == 0) {
        float b = 0.f, c = 0.f;
        #pragma unroll
        for (int q = 0; q < 8; q++) { b += red[0][q]; c += red[1][q]; }
        // positives (<= 7 softplus evals): do serially here
        float a = 0.f;
        for (int j = lo; j < hi; j++) {
            if (j == i) continue;
            a += sp_f(10.f * (inter - srow[j]));
        }
        g_rowloss[i] = 0.2f * a / kf + 0.05f * b / fmaxf(c, 1.f);
    }
}

// ---------------------------------------------------------------------------
// Kernel 3: deterministic final reduction
// ---------------------------------------------------------------------------
__global__ __launch_bounds__(256) void final_reduce(float* __restrict__ out) {
    __shared__ float sh[256];
    const int tid = threadIdx.x;
    float v = 0.f;
    for (int j = tid; j < NN; j += 256) v += g_rowloss[j];
    sh[tid] = v;
    __syncthreads();
    #pragma unroll
    for (int s = 128; s > 0; s >>= 1) {
        if (tid < s) sh[tid] += sh[tid + s];
        __syncthreads();
    }
    if (tid == 0) out[0] = sh[0] * (1.0f / NN);
}

// ---------------------------------------------------------------------------
extern "C" void kernel_launch(void* const* d_in, const int* in_sizes, int n_in,
                              void* d_out, int out_size) {
    const float* X = (const float*)d_in[0];
    const int* ni_ptr = (n_in > 2) ? (const int*)d_in[2] : nullptr;

    gemm_xxt<<<NTRI, 256>>>(X);
    row_loss<<<NN, 256>>>(ni_ptr);
    final_reduce<<<1, 256>>>((float*)d_out);
}

// round 4
// speedup vs baseline: 2.0654x; 1.3580x over previous
#include <cuda_runtime.h>
#include <cuda_bf16.h>
#include <cstdint>

#define NN 4096
#define DD 128
#define TS 128
#define NTILE (NN / TS)                  // 32
#define NTRI  (NTILE * (NTILE + 1) / 2)  // 528
#define PITCH 272                        // bytes per smem row (128 bf16 + 8 pad)

__device__ float g_sim[(size_t)NN * NN];
__device__ float g_rowloss[NN];
__device__ __nv_bfloat16 g_H[(size_t)NN * DD];
__device__ __nv_bfloat16 g_L[(size_t)NN * DD];

// ---------------------------------------------------------------------------
__device__ __forceinline__ uint32_t smem_to_u32(const void* p) {
    uint32_t a;
    asm("{ .reg .u64 t; cvta.to.shared.u64 t, %1; cvt.u32.u64 %0, t; }" : "=r"(a) : "l"(p));
    return a;
}
__device__ __forceinline__ void ldsm4(uint32_t* r, uint32_t addr) {
    asm volatile("ldmatrix.sync.aligned.m8n8.x4.shared.b16 {%0,%1,%2,%3}, [%4];"
                 : "=r"(r[0]), "=r"(r[1]), "=r"(r[2]), "=r"(r[3]) : "r"(addr));
}
__device__ __forceinline__ void mma16816(float* c, const uint32_t* a,
                                         uint32_t b0, uint32_t b1) {
    asm volatile("mma.sync.aligned.m16n8k16.row.col.f32.bf16.bf16.f32 "
                 "{%0,%1,%2,%3}, {%4,%5,%6,%7}, {%8,%9}, {%0,%1,%2,%3};"
                 : "+f"(c[0]), "+f"(c[1]), "+f"(c[2]), "+f"(c[3])
                 : "r"(a[0]), "r"(a[1]), "r"(a[2]), "r"(a[3]), "r"(b0), "r"(b1));
}

// ---------------------------------------------------------------------------
// Kernel 0: bf16 split  Xh = bf16(x), Xl = bf16(x - Xh)
// ---------------------------------------------------------------------------
__global__ __launch_bounds__(256) void split_bf16(const float* __restrict__ X) {
    int idx = blockIdx.x * 256 + threadIdx.x;           // over NN*DD/4
    float4 v = ((const float4*)X)[idx];
    float xs[4] = {v.x, v.y, v.z, v.w};
    __nv_bfloat16 h[4], l[4];
    #pragma unroll
    for (int e = 0; e < 4; e++) {
        h[e] = __float2bfloat16_rn(xs[e]);
        l[e] = __float2bfloat16_rn(xs[e] - __bfloat162float(h[e]));
    }
    ((ushort4*)g_H)[idx] = make_ushort4(*(unsigned short*)&h[0], *(unsigned short*)&h[1],
                                        *(unsigned short*)&h[2], *(unsigned short*)&h[3]);
    ((ushort4*)g_L)[idx] = make_ushort4(*(unsigned short*)&l[0], *(unsigned short*)&l[1],
                                        *(unsigned short*)&l[2], *(unsigned short*)&l[3]);
}

// ---------------------------------------------------------------------------
// Kernel 1: sim = Xh·Xhᵀ + Xh·Xlᵀ + Xl·Xhᵀ via HMMA (mma.sync bf16),
// upper-triangular 128x128 tiles with mirrored write-back.
// smem: 4 operand panels (A_H, A_L, B_H, B_L), 128 rows x 272B each.
// ---------------------------------------------------------------------------
#define AH_OFF 0
#define AL_OFF (128 * PITCH)          // 34816
#define BH_OFF (2 * 128 * PITCH)      // 69632
#define BL_OFF (3 * 128 * PITCH)      // 104448
#define SMEM_TOTAL (4 * 128 * PITCH)  // 139264

__global__ __launch_bounds__(256, 1) void gemm_tc() {
    extern __shared__ char smem[];
    const uint32_t sb = smem_to_u32(smem);
    const int tid = threadIdx.x;
    const int wid = tid >> 5;
    const int lane = tid & 31;

    // triangular decode
    int rem = blockIdx.x, by = 0;
    while (rem >= (NTILE - by)) { rem -= (NTILE - by); by++; }
    const int bx = by + rem;
    const int br = by * TS, bc = bx * TS;

    // load 4 operand panels (row-major bf16, padded pitch)
    {
        const __nv_bfloat16* srcs[4] = {
            g_H + (size_t)br * DD, g_L + (size_t)br * DD,
            g_H + (size_t)bc * DD, g_L + (size_t)bc * DD};
        const int offs[4] = {AH_OFF, AL_OFF, BH_OFF, BL_OFF};
        #pragma unroll
        for (int b = 0; b < 4; b++) {
            #pragma unroll
            for (int it = 0; it < 8; it++) {
                int idx = tid + it * 256;        // 0..2047
                int row = idx >> 4;
                int c16 = idx & 15;
                *(uint4*)(smem + offs[b] + row * PITCH + c16 * 16) =
                    *(const uint4*)(srcs[b] + (size_t)row * DD + c16 * 8);
            }
        }
    }
    __syncthreads();

    const int wm = wid & 3;    // 4 warps over M: rows wm*32..+31
    const int wn = wid >> 2;   // 2 warps over N: cols wn*64..+63

    float acc[2][8][4];
    #pragma unroll
    for (int ma = 0; ma < 2; ma++)
        #pragma unroll
        for (int na = 0; na < 8; na++)
            #pragma unroll
            for (int q = 0; q < 4; q++) acc[ma][na][q] = 0.f;

    const uint32_t lrow = lane & 15;
    const uint32_t lcol = (lane >> 4) * 16;
    const uint32_t aoff[3] = {AH_OFF, AH_OFF, AL_OFF};
    const uint32_t boff[3] = {BH_OFF, BL_OFF, BH_OFF};

    #pragma unroll
    for (int p = 0; p < 3; p++) {
        const uint32_t abase = sb + aoff[p] + (wm * 32 + lrow) * PITCH + lcol;
        const uint32_t bbase = sb + boff[p] + (wn * 64 + lrow) * PITCH + lcol;
        #pragma unroll
        for (int ks = 0; ks < 8; ks++) {
            uint32_t a0[4], a1[4], bf[4][4];
            ldsm4(a0, abase + ks * 32);
            ldsm4(a1, abase + 16 * PITCH + ks * 32);
            #pragma unroll
            for (int nb = 0; nb < 4; nb++)
                ldsm4(bf[nb], bbase + nb * 16 * PITCH + ks * 32);
            #pragma unroll
            for (int nb = 0; nb < 4; nb++) {
                mma16816(acc[0][2 * nb],     a0, bf[nb][0], bf[nb][2]);
                mma16816(acc[0][2 * nb + 1], a0, bf[nb][1], bf[nb][3]);
                mma16816(acc[1][2 * nb],     a1, bf[nb][0], bf[nb][2]);
                mma16816(acc[1][2 * nb + 1], a1, bf[nb][1], bf[nb][3]);
            }
        }
    }

    // ---- normal (row-major) store ----
    const int quad = lane >> 2, ql = lane & 3;
    #pragma unroll
    for (int ma = 0; ma < 2; ma++) {
        #pragma unroll
        for (int h = 0; h < 2; h++) {
            const int row = br + wm * 32 + ma * 16 + h * 8 + quad;
            float* dst = g_sim + (size_t)row * NN + bc + wn * 64 + ql * 2;
            #pragma unroll
            for (int na = 0; na < 8; na++) {
                float2 v = make_float2(acc[ma][na][2 * h], acc[ma][na][2 * h + 1]);
                *(float2*)(dst + na * 8) = v;
            }
        }
    }

    // ---- mirrored (transposed) store via smem for off-diagonal tiles ----
    if (bx != by) {
        float* smf = (float*)smem;             // reuse operand smem: 128x132 fp32
        __syncthreads();                       // all warps done reading operands
        #pragma unroll
        for (int ma = 0; ma < 2; ma++)
            #pragma unroll
            for (int h = 0; h < 2; h++) {
                const int rl = wm * 32 + ma * 16 + h * 8 + quad;
                #pragma unroll
                for (int na = 0; na < 8; na++) {
                    const int cl = wn * 64 + na * 8 + ql * 2;
                    smf[cl * 132 + rl]       = acc[ma][na][2 * h];
                    smf[(cl + 1) * 132 + rl] = acc[ma][na][2 * h + 1];
                }
            }
        __syncthreads();
        for (int idx = tid; idx < 128 * 32; idx += 256) {
            const int col = idx >> 5, r4 = (idx & 31) * 4;
            float4 v = *(const float4*)(smf + col * 132 + r4);
            *(float4*)(g_sim + (size_t)(bc + col) * NN + br + r4) = v;
        }
    }
}

// ---------------------------------------------------------------------------
// Kernel 2: per-row stats + loss. One CTA (512 threads) per row.
// ---------------------------------------------------------------------------
__device__ __forceinline__ float warpSum(float v) {
    #pragma unroll
    for (int o = 16; o > 0; o >>= 1) v += __shfl_down_sync(0xffffffffu, v, o);
    return v;
}
__device__ __forceinline__ float sp_f(float x) {
    float e = __expf(-fabsf(x));
    return fmaxf(x, 0.0f) + __logf(1.0f + e);
}

__global__ __launch_bounds__(512) void row_loss(const int* __restrict__ ni_ptr) {
    __shared__ float srow[NN];
    __shared__ float red[2][16];
    __shared__ float params[3];

    const int i   = blockIdx.x;
    const int tid = threadIdx.x;
    const int ni  = ni_ptr ? *ni_ptr : 8;
    const int lo  = (i / ni) * ni;
    const int hi  = lo + ni;
    const float4* row4 = (const float4*)(g_sim + (size_t)i * NN);

    float sum = 0.f, sq = 0.f;
    for (int j4 = tid; j4 < NN / 4; j4 += 512) {
        float4 v = row4[j4];
        ((float4*)srow)[j4] = v;
        sum += (v.x + v.y) + (v.z + v.w);
        sq  += (v.x * v.x + v.y * v.y) + (v.z * v.z + v.w * v.w);
    }
    sum = warpSum(sum); sq = warpSum(sq);
    const int lane = tid & 31, w = tid >> 5;
    if (lane == 0) { red[0][w] = sum; red[1][w] = sq; }
    __syncthreads();
    if (tid == 0) {
        float S = 0.f, Q = 0.f;
        #pragma unroll
        for (int q = 0; q < 16; q++) { S += red[0][q]; Q += red[1][q]; }
        float ps = 0.f, pq = 0.f, pm = 1e30f;
        for (int j = lo; j < hi; j++) {
            if (j == i) continue;
            float s = srow[j];
            ps += s; pq += s * s; pm = fminf(pm, s);
        }
        float sii = srow[i];
        float kf  = (float)(ni - 1);
        float ncf = (float)(NN - ni);
        float ns = S - ps - sii;
        float nq = Q - pq - sii * sii;
        float pmean = ps / kf;
        float pstd  = sqrtf(fmaxf(pq / kf - pmean * pmean, 0.f));
        float nmean = ns / ncf;
        float nstd  = sqrtf(fmaxf(nq / ncf - nmean * nmean, 0.f));
        float inter = (nstd * pmean + pstd * nmean) / (pstd + nstd);
        inter = 0.8f * inter + 0.1f;
        params[0] = inter;
        params[1] = pm - 0.05f;
        params[2] = kf;
    }
    __syncthreads();
    const float inter = params[0], thr = params[1], kf = params[2];

    float nl = 0.f, cnt = 0.f;
    for (int j4 = tid; j4 < NN / 4; j4 += 512) {
        float4 v = ((const float4*)srow)[j4];
        int jb = j4 * 4;
        float vs[4] = {v.x, v.y, v.z, v.w};
        #pragma unroll
        for (int e = 0; e < 4; e++) {
            int j = jb + e;
            bool keep = !((j >= lo) & (j < hi)) & (vs[e] > thr);
            if (keep) {
                nl += sp_f(40.f * (vs[e] - inter));
                cnt += 1.f;
            }
        }
    }
    nl = warpSum(nl); cnt = warpSum(cnt);
    if (lane == 0) { red[0][w] = nl; red[1][w] = cnt; }
    __syncthreads();
    if (tid == 0) {
        float b = 0.f, c = 0.f;
        #pragma unroll
        for (int q = 0; q < 16; q++) { b += red[0][q]; c += red[1][q]; }
        float a = 0.f;
        for (int j = lo; j < hi; j++) {
            if (j == i) continue;
            a += sp_f(10.f * (inter - srow[j]));
        }
        g_rowloss[i] = 0.2f * a / kf + 0.05f * b / fmaxf(c, 1.f);
    }
}

// ---------------------------------------------------------------------------
// Kernel 3: deterministic final reduction
// ---------------------------------------------------------------------------
__global__ __launch_bounds__(256) void final_reduce(float* __restrict__ out) {
    __shared__ float sh[256];
    const int tid = threadIdx.x;
    float v = 0.f;
    for (int j = tid; j < NN; j += 256) v += g_rowloss[j];
    sh[tid] = v;
    __syncthreads();
    #pragma unroll
    for (int s = 128; s > 0; s >>= 1) {
        if (tid < s) sh[tid] += sh[tid + s];
        __syncthreads();
    }
    if (tid == 0) out[0] = sh[0] * (1.0f / NN);
}

// ---------------------------------------------------------------------------
extern "C" void kernel_launch(void* const* d_in, const int* in_sizes, int n_in,
                              void* d_out, int out_size) {
    const float* X = (const float*)d_in[0];
    const int* ni_ptr = (n_in > 2) ? (const int*)d_in[2] : nullptr;

    cudaFuncSetAttribute(gemm_tc, cudaFuncAttributeMaxDynamicSharedMemorySize, SMEM_TOTAL);

    split_bf16<<<NN * DD / 1024, 256>>>(X);
    gemm_tc<<<NTRI, 256, SMEM_TOTAL>>>();
    row_loss<<<NN, 512>>>(ni_ptr);
    final_reduce<<<1, 256>>>((float*)d_out);
}